// round 1
// baseline (speedup 1.0000x reference)
#include <cuda_runtime.h>
#include <math.h>

#define BB 2
#define SS 2048
#define HH 32
#define HD 64
#define MD 2048
#define MTOT (BB*SS)

// scratch (static device globals — no allocation)
__device__ float g_q[BB*HH*SS*HD];
__device__ float g_k[BB*HH*SS*HD];
__device__ float g_v[BB*HH*SS*HD];
__device__ float g_ctx[MTOT*MD];
__device__ float g_biastab[HH*4096];

// ---------------------------------------------------------------------------
// Relative-position bucket: exact integer reimplementation of the T5 formula.
// sub-bucket thresholds derived analytically from 8 + floor(8*log(d/8)/log(16)):
//   d<8: d ; [8,11]:8 ; [12,15]:9 ; [16,22]:10 ; [23,31]:11 ; [32,45]:12 ;
//   [46,63]:13 ; [64,90]:14 ; [91,inf):15
// ---------------------------------------------------------------------------
__device__ __forceinline__ int rel_bucket(int dist /* = k - q */) {
    int rel = dist > 0 ? 16 : 0;
    int d = abs(dist);
    int sb;
    if (d < 8)       sb = d;
    else if (d < 12) sb = 8;
    else if (d < 16) sb = 9;
    else if (d < 23) sb = 10;
    else if (d < 32) sb = 11;
    else if (d < 46) sb = 12;
    else if (d < 64) sb = 13;
    else if (d < 91) sb = 14;
    else             sb = 15;
    return rel + sb;
}

__global__ void bias_table_kernel(const float* __restrict__ rel_bias) {
    int idx = blockIdx.x * blockDim.x + threadIdx.x; // over HH*4095
    if (idx >= HH * 4095) return;
    int h = idx / 4095;
    int di = idx % 4095;         // di = dist + 2047, dist in [-2047, 2047]
    int bucket = rel_bucket(di - 2047);
    g_biastab[h * 4096 + di] = rel_bias[bucket * HH + h];
}

// ---------------------------------------------------------------------------
// position_bias materialization: out_bias[h][q][k] = tab[h][k-q+2047]
// pure streaming write, float4 vectorized
// ---------------------------------------------------------------------------
__global__ void bias_write_kernel(float* __restrict__ out_bias) {
    long long idx = (long long)blockIdx.x * blockDim.x + threadIdx.x; // float4 idx
    const int per_row4 = SS / 4;                 // 512
    long long row = idx / per_row4;              // h*SS + q
    int k = (int)(idx % per_row4) * 4;
    int h = (int)(row >> 11);
    int q = (int)(row & (SS - 1));
    const float* tab = &g_biastab[h * 4096 + 2047 - q];
    float4 v;
    v.x = tab[k + 0]; v.y = tab[k + 1]; v.z = tab[k + 2]; v.w = tab[k + 3];
    reinterpret_cast<float4*>(out_bias)[idx] = v;
}

// ---------------------------------------------------------------------------
// C[m,n] = sum_k A[m,k] * B[n,k]   (both row-major, NT gemm)
// 64x64 tile, BK=16, 256 threads, 4x4 per thread.
// PERM=true writes C into [b, h, s, d] layout (for q/k/v).
// ---------------------------------------------------------------------------
template<bool PERM>
__global__ void __launch_bounds__(256) gemm_nt(const float* __restrict__ A,
                                               const float* __restrict__ Bm,
                                               float* __restrict__ C,
                                               int M, int N, int K)
{
    __shared__ float As[16][64];
    __shared__ float Bs[16][64];
    const int t  = threadIdx.x;
    const int tx = t & 15, ty = t >> 4;
    const int m0 = blockIdx.y * 64, n0 = blockIdx.x * 64;
    const int lrow = t >> 2;          // 0..63
    const int lcv  = (t & 3) * 4;     // 0,4,8,12
    const float* Ag = A  + (size_t)(m0 + lrow) * K + lcv;
    const float* Bg = Bm + (size_t)(n0 + lrow) * K + lcv;
    float acc[4][4] = {};

    for (int k0 = 0; k0 < K; k0 += 16) {
        float4 a = *reinterpret_cast<const float4*>(Ag + k0);
        float4 b = *reinterpret_cast<const float4*>(Bg + k0);
        As[lcv + 0][lrow] = a.x; As[lcv + 1][lrow] = a.y;
        As[lcv + 2][lrow] = a.z; As[lcv + 3][lrow] = a.w;
        Bs[lcv + 0][lrow] = b.x; Bs[lcv + 1][lrow] = b.y;
        Bs[lcv + 2][lrow] = b.z; Bs[lcv + 3][lrow] = b.w;
        __syncthreads();
        #pragma unroll
        for (int kk = 0; kk < 16; kk++) {
            float4 av = *reinterpret_cast<const float4*>(&As[kk][ty * 4]);
            float4 bv = *reinterpret_cast<const float4*>(&Bs[kk][tx * 4]);
            acc[0][0] += av.x * bv.x; acc[0][1] += av.x * bv.y;
            acc[0][2] += av.x * bv.z; acc[0][3] += av.x * bv.w;
            acc[1][0] += av.y * bv.x; acc[1][1] += av.y * bv.y;
            acc[1][2] += av.y * bv.z; acc[1][3] += av.y * bv.w;
            acc[2][0] += av.z * bv.x; acc[2][1] += av.z * bv.y;
            acc[2][2] += av.z * bv.z; acc[2][3] += av.z * bv.w;
            acc[3][0] += av.w * bv.x; acc[3][1] += av.w * bv.y;
            acc[3][2] += av.w * bv.z; acc[3][3] += av.w * bv.w;
        }
        __syncthreads();
    }

    #pragma unroll
    for (int i = 0; i < 4; i++) {
        int m = m0 + ty * 4 + i;
        float4 r = make_float4(acc[i][0], acc[i][1], acc[i][2], acc[i][3]);
        if (PERM) {
            int b = m >> 11, s = m & (SS - 1);
            int h = n0 >> 6;
            size_t off = (((size_t)(b * HH + h) * SS + s) * HD) + tx * 4;
            *reinterpret_cast<float4*>(C + off) = r;
        } else {
            *reinterpret_cast<float4*>(C + (size_t)m * N + n0 + tx * 4) = r;
        }
    }
}

// ---------------------------------------------------------------------------
// Fused flash attention: one block = one (b,h) x 64-row q tile.
// Q,K stored transposed in smem ([d][row]); V natural ([row][d]); P [q][k].
// ---------------------------------------------------------------------------
__global__ void __launch_bounds__(256) attn_kernel()
{
    extern __shared__ float sm[];
    float (*Qs)[64] = reinterpret_cast<float(*)[64]>(sm);            // [d][qrow]
    float (*Ks)[64] = reinterpret_cast<float(*)[64]>(sm + 4096);     // [d][krow]
    float (*Vs)[64] = reinterpret_cast<float(*)[64]>(sm + 8192);     // [krow][d]
    float (*Ps)[64] = reinterpret_cast<float(*)[64]>(sm + 12288);    // [qrow][krow]
    float* bsm = sm + 16384;                                          // [128]

    const int t  = threadIdx.x;
    const int tx = t & 15, ty = t >> 4;
    const int bh = blockIdx.y;
    const int h  = bh & (HH - 1);
    const int b  = bh >> 5;
    const int q0 = blockIdx.x * 64;
    const float* qg = g_q + (size_t)bh * SS * HD;
    const float* kg = g_k + (size_t)bh * SS * HD;
    const float* vg = g_v + (size_t)bh * SS * HD;
    const float* tabh = g_biastab + h * 4096;

    // load Q tile transposed
    #pragma unroll
    for (int rep = 0; rep < 4; rep++) {
        int lin = t + rep * 256;
        int row = lin >> 4;
        int cv  = (lin & 15) * 4;
        float4 a = *reinterpret_cast<const float4*>(&qg[(size_t)(q0 + row) * HD + cv]);
        Qs[cv + 0][row] = a.x; Qs[cv + 1][row] = a.y;
        Qs[cv + 2][row] = a.z; Qs[cv + 3][row] = a.w;
    }

    float m_i[4], l_i[4], o[4][4];
    #pragma unroll
    for (int i = 0; i < 4; i++) {
        m_i[i] = -1e30f; l_i[i] = 0.f;
        #pragma unroll
        for (int j = 0; j < 4; j++) o[i][j] = 0.f;
    }

    for (int k0 = 0; k0 < SS; k0 += 64) {
        // load K tile transposed + V tile natural
        #pragma unroll
        for (int rep = 0; rep < 4; rep++) {
            int lin = t + rep * 256;
            int row = lin >> 4;
            int cv  = (lin & 15) * 4;
            float4 a = *reinterpret_cast<const float4*>(&kg[(size_t)(k0 + row) * HD + cv]);
            Ks[cv + 0][row] = a.x; Ks[cv + 1][row] = a.y;
            Ks[cv + 2][row] = a.z; Ks[cv + 3][row] = a.w;
            float4 vv = *reinterpret_cast<const float4*>(&vg[(size_t)(k0 + row) * HD + cv]);
            *reinterpret_cast<float4*>(&Vs[row][cv]) = vv;
        }
        if (t < 128) bsm[t] = tabh[k0 - q0 + 1984 + t];
        __syncthreads();

        // S = Q K^T  (64x64x64)
        float sc[4][4] = {};
        #pragma unroll 8
        for (int kk = 0; kk < 64; kk++) {
            float4 qv = *reinterpret_cast<const float4*>(&Qs[kk][ty * 4]);
            float4 kv = *reinterpret_cast<const float4*>(&Ks[kk][tx * 4]);
            sc[0][0] += qv.x * kv.x; sc[0][1] += qv.x * kv.y;
            sc[0][2] += qv.x * kv.z; sc[0][3] += qv.x * kv.w;
            sc[1][0] += qv.y * kv.x; sc[1][1] += qv.y * kv.y;
            sc[1][2] += qv.y * kv.z; sc[1][3] += qv.y * kv.w;
            sc[2][0] += qv.z * kv.x; sc[2][1] += qv.z * kv.y;
            sc[2][2] += qv.z * kv.z; sc[2][3] += qv.z * kv.w;
            sc[3][0] += qv.w * kv.x; sc[3][1] += qv.w * kv.y;
            sc[3][2] += qv.w * kv.z; sc[3][3] += qv.w * kv.w;
        }

        // bias + online softmax (row reduce across 16 lanes: xor 1/2/4/8)
        #pragma unroll
        for (int i = 0; i < 4; i++) {
            float mx = -1e30f;
            #pragma unroll
            for (int j = 0; j < 4; j++) {
                sc[i][j] += bsm[63 + tx * 4 + j - ty * 4 - i];
                mx = fmaxf(mx, sc[i][j]);
            }
            mx = fmaxf(mx, __shfl_xor_sync(0xffffffffu, mx, 1));
            mx = fmaxf(mx, __shfl_xor_sync(0xffffffffu, mx, 2));
            mx = fmaxf(mx, __shfl_xor_sync(0xffffffffu, mx, 4));
            mx = fmaxf(mx, __shfl_xor_sync(0xffffffffu, mx, 8));
            float mnew  = fmaxf(m_i[i], mx);
            float scale = expf(m_i[i] - mnew);
            float sum = 0.f;
            #pragma unroll
            for (int j = 0; j < 4; j++) {
                float p = expf(sc[i][j] - mnew);
                sc[i][j] = p; sum += p;
            }
            sum += __shfl_xor_sync(0xffffffffu, sum, 1);
            sum += __shfl_xor_sync(0xffffffffu, sum, 2);
            sum += __shfl_xor_sync(0xffffffffu, sum, 4);
            sum += __shfl_xor_sync(0xffffffffu, sum, 8);
            l_i[i] = l_i[i] * scale + sum;
            m_i[i] = mnew;
            #pragma unroll
            for (int j = 0; j < 4; j++) o[i][j] *= scale;
            *reinterpret_cast<float4*>(&Ps[ty * 4 + i][tx * 4]) =
                make_float4(sc[i][0], sc[i][1], sc[i][2], sc[i][3]);
        }
        __syncthreads();

        // O += P V
        #pragma unroll 8
        for (int kk = 0; kk < 64; kk++) {
            float4 vv = *reinterpret_cast<const float4*>(&Vs[kk][tx * 4]);
            #pragma unroll
            for (int i = 0; i < 4; i++) {
                float p = Ps[ty * 4 + i][kk];
                o[i][0] += p * vv.x; o[i][1] += p * vv.y;
                o[i][2] += p * vv.z; o[i][3] += p * vv.w;
            }
        }
        __syncthreads();
    }

    // epilogue: ctx[b, q, h*64+d] = o / l
    #pragma unroll
    for (int i = 0; i < 4; i++) {
        float inv = 1.0f / l_i[i];
        int row = q0 + ty * 4 + i;
        size_t off = ((size_t)(b * SS + row)) * MD + h * HD + tx * 4;
        *reinterpret_cast<float4*>(g_ctx + off) =
            make_float4(o[i][0] * inv, o[i][1] * inv, o[i][2] * inv, o[i][3] * inv);
    }
}

// ---------------------------------------------------------------------------

extern "C" void kernel_launch(void* const* d_in, const int* in_sizes, int n_in,
                              void* d_out, int out_size)
{
    (void)in_sizes; (void)n_in; (void)out_size;
    const float* x  = (const float*)d_in[0];
    const float* wq = (const float*)d_in[1];
    const float* wk = (const float*)d_in[2];
    const float* wv = (const float*)d_in[3];
    const float* wo = (const float*)d_in[4];
    const float* rb = (const float*)d_in[5];
    float* out      = (float*)d_out;
    float* out_bias = out + (size_t)BB * SS * MD;

    float *qp, *kp, *vp, *cp;
    cudaGetSymbolAddress((void**)&qp, g_q);
    cudaGetSymbolAddress((void**)&kp, g_k);
    cudaGetSymbolAddress((void**)&vp, g_v);
    cudaGetSymbolAddress((void**)&cp, g_ctx);

    cudaFuncSetAttribute(attn_kernel, cudaFuncAttributeMaxDynamicSharedMemorySize, 66048);

    bias_table_kernel<<<(HH * 4095 + 255) / 256, 256>>>(rb);

    dim3 gg(MD / 64, MTOT / 64);
    gemm_nt<true><<<gg, 256>>>(x, wq, qp, MTOT, MD, MD);
    gemm_nt<true><<<gg, 256>>>(x, wk, kp, MTOT, MD, MD);
    gemm_nt<true><<<gg, 256>>>(x, wv, vp, MTOT, MD, MD);

    attn_kernel<<<dim3(SS / 64, BB * HH), 256, 66048>>>();

    gemm_nt<false><<<gg, 256>>>(cp, wo, out, MTOT, MD, MD);

    long long nb4 = (long long)HH * SS * (SS / 4);
    bias_write_kernel<<<(unsigned)(nb4 / 256), 256>>>(out_bias);
}

// round 3
// speedup vs baseline: 1.4916x; 1.4916x over previous
#include <cuda_runtime.h>
#include <cuda_bf16.h>
#include <cstdint>
#include <math.h>

#define BB 2
#define SS 2048
#define HH 32
#define HD 64
#define MD 2048
#define MTOT (BB*SS)

// scratch (static device globals — no allocation)
__device__ float g_q[BB*HH*SS*HD];
__device__ float g_k[BB*HH*SS*HD];
__device__ float g_v[BB*HH*SS*HD];
__device__ float g_ctx[MTOT*MD];
__device__ float g_biastab[HH*4096];

__device__ __forceinline__ uint32_t smem_to_u32(const void* smem_ptr) {
    uint32_t addr;
    asm("{ .reg .u64 tmp; cvta.to.shared.u64 tmp, %1; cvt.u32.u64 %0, tmp; }"
        : "=r"(addr) : "l"(smem_ptr));
    return addr;
}

// ===========================================================================
// bf16 hi/lo split-convert + swizzled smem store for one float4 (8B hi + 8B lo)
// hi = truncate-to-bf16(f) (exact bits), lo = rn-bf16(f - hi)
// ===========================================================================
__device__ __forceinline__ void cvt_store(char* smem_hi, char* smem_lo,
                                          uint32_t off, float4 f) {
    uint32_t ux = __float_as_uint(f.x), uy = __float_as_uint(f.y),
             uz = __float_as_uint(f.z), uw = __float_as_uint(f.w);
    uint32_t hi01 = __byte_perm(ux, uy, 0x7632);
    uint32_t hi23 = __byte_perm(uz, uw, 0x7632);
    float lx = f.x - __uint_as_float(ux & 0xffff0000u);
    float ly = f.y - __uint_as_float(uy & 0xffff0000u);
    float lz = f.z - __uint_as_float(uz & 0xffff0000u);
    float lw = f.w - __uint_as_float(uw & 0xffff0000u);
    uint32_t lo01, lo23;
    asm("cvt.rn.bf16x2.f32 %0, %1, %2;" : "=r"(lo01) : "f"(ly), "f"(lx));
    asm("cvt.rn.bf16x2.f32 %0, %1, %2;" : "=r"(lo23) : "f"(lw), "f"(lz));
    uint32_t sw = off ^ ((off >> 3) & 0x70);
    *reinterpret_cast<uint2*>(smem_hi + sw) = make_uint2(hi01, hi23);
    *reinterpret_cast<uint2*>(smem_lo + sw) = make_uint2(lo01, lo23);
}

// thread t covers (row = t>>1, 32-float half = (t&1)) of a 128x64 fp32 chunk
__device__ __forceinline__ void load_regs(const float* __restrict__ g,
                                          int row0, int k0, int t, float4* v) {
    const int r = t >> 1;
    const int he = (t & 1) * 32;
    const float4* src = reinterpret_cast<const float4*>(
        g + (size_t)(row0 + r) * 2048 + k0 + he);
    #pragma unroll
    for (int i = 0; i < 8; i++) v[i] = src[i];
}

__device__ __forceinline__ void store_regs(char* hi, char* lo, int t,
                                           const float4* v) {
    const int r = t >> 1;
    const int he = (t & 1) * 32;
    const uint32_t base = (uint32_t)(r * 128 + he * 2);
    #pragma unroll
    for (int i = 0; i < 8; i++) cvt_store(hi, lo, base + i * 8, v[i]);
}

__device__ __forceinline__ void ldx4(uint32_t* r, uint32_t addr) {
    asm volatile("ldmatrix.sync.aligned.m8n8.x4.shared.b16 {%0,%1,%2,%3}, [%4];"
                 : "=r"(r[0]), "=r"(r[1]), "=r"(r[2]), "=r"(r[3]) : "r"(addr));
}

__device__ __forceinline__ void mma_bf16(float* d, const uint32_t* a,
                                         uint32_t b0, uint32_t b1) {
    asm volatile(
        "mma.sync.aligned.m16n8k16.row.col.f32.bf16.bf16.f32 "
        "{%0,%1,%2,%3}, {%4,%5,%6,%7}, {%8,%9}, {%0,%1,%2,%3};"
        : "+f"(d[0]), "+f"(d[1]), "+f"(d[2]), "+f"(d[3])
        : "r"(a[0]), "r"(a[1]), "r"(a[2]), "r"(a[3]), "r"(b0), "r"(b1));
}

// ===========================================================================
// bf16x3 tensor-core GEMM via mma.sync: C[4096,2048] = A @ B^T (both row-major)
// 128x128 tile/block, K-chunk 64, double-buffered SW128 bf16 hi/lo smem.
// PERM=true scatters C into [b, h, s, d] (q/k/v layout).
// smem: 2 stages x { Ahi 16K | Alo 16K | Bhi 16K | Blo 16K }
// ===========================================================================
#define GSMEM_BYTES (2 * 65536)

template<bool PERM>
__global__ void __launch_bounds__(256, 1) gemm_mma(const float* __restrict__ A,
                                                   const float* __restrict__ Bm,
                                                   float* __restrict__ C)
{
    extern __shared__ char smem[];
    const uint32_t smem_u = smem_to_u32(smem);
    const int tid = threadIdx.x;
    const int l   = tid & 31;
    const int w   = tid >> 5;
    const int warpm = w >> 1;        // 0..3 -> 32 rows each
    const int warpn = w & 1;         // 0..1 -> 64 cols each
    const int grp = l >> 3, lr = l & 7;

    const int m0 = (blockIdx.x >> 4) * 128;
    const int n0 = (blockIdx.x & 15) * 128;

    // preload chunk 0 into stage 0
    {
        float4 va[8], vb[8];
        load_regs(A,  m0, 0, tid, va);
        load_regs(Bm, n0, 0, tid, vb);
        store_regs(smem,         smem + 16384, tid, va);
        store_regs(smem + 32768, smem + 49152, tid, vb);
    }
    __syncthreads();

    float acc[2][8][4];
    #pragma unroll
    for (int mt = 0; mt < 2; mt++)
        #pragma unroll
        for (int nt = 0; nt < 8; nt++)
            #pragma unroll
            for (int i = 0; i < 4; i++) acc[mt][nt][i] = 0.f;

    // precompute per-lane ldmatrix byte offsets (within a 16KB tile)
    // A: row = warpm*32 + mt*16 + lr + (grp&1)*8 ; col16 = 2*ks + (grp>>1)
    // B: row = warpn*64 + j*16  + lr + (grp>>1)*8; col16 = 2*ks + (grp&1)
    uint32_t a_row[2], b_row[4];
    #pragma unroll
    for (int mt = 0; mt < 2; mt++)
        a_row[mt] = (uint32_t)((warpm * 32 + mt * 16 + lr + (grp & 1) * 8) * 128);
    #pragma unroll
    for (int j = 0; j < 4; j++)
        b_row[j] = (uint32_t)((warpn * 64 + j * 16 + lr + (grp >> 1) * 8) * 128);
    const uint32_t a_c16 = (uint32_t)(grp >> 1) * 16;
    const uint32_t b_c16 = (uint32_t)(grp & 1) * 16;

    for (int c = 0; c < 32; c++) {
        const uint32_t cur = smem_u + (uint32_t)(c & 1) * 65536;

        // issue next chunk's global loads early (latency hidden by MMA below)
        float4 va[8], vb[8];
        if (c + 1 < 32) {
            load_regs(A,  m0, (c + 1) * 64, tid, va);
            load_regs(Bm, n0, (c + 1) * 64, tid, vb);
        }

        const uint32_t uAh = cur, uAl = cur + 16384,
                       uBh = cur + 32768, uBl = cur + 49152;

        #pragma unroll
        for (int ks = 0; ks < 4; ks++) {
            uint32_t ah[2][4], al[2][4];
            #pragma unroll
            for (int mt = 0; mt < 2; mt++) {
                uint32_t off = a_row[mt] + (uint32_t)(ks * 32) + a_c16;
                off ^= (off >> 3) & 0x70;
                ldx4(ah[mt], uAh + off);
                ldx4(al[mt], uAl + off);
            }
            uint32_t bh[4][4], bl[4][4];
            #pragma unroll
            for (int j = 0; j < 4; j++) {
                uint32_t off = b_row[j] + (uint32_t)(ks * 32) + b_c16;
                off ^= (off >> 3) & 0x70;
                ldx4(bh[j], uBh + off);
                ldx4(bl[j], uBl + off);
            }
            #pragma unroll
            for (int mt = 0; mt < 2; mt++) {
                #pragma unroll
                for (int j = 0; j < 4; j++) {
                    // n-tile 2j
                    mma_bf16(acc[mt][2*j],   ah[mt], bh[j][0], bh[j][1]);
                    mma_bf16(acc[mt][2*j],   ah[mt], bl[j][0], bl[j][1]);
                    mma_bf16(acc[mt][2*j],   al[mt], bh[j][0], bh[j][1]);
                    // n-tile 2j+1
                    mma_bf16(acc[mt][2*j+1], ah[mt], bh[j][2], bh[j][3]);
                    mma_bf16(acc[mt][2*j+1], ah[mt], bl[j][2], bl[j][3]);
                    mma_bf16(acc[mt][2*j+1], al[mt], bh[j][2], bh[j][3]);
                }
            }
        }
        __syncthreads();
        if (c + 1 < 32) {
            char* nxt = smem + ((c + 1) & 1) * 65536;
            store_regs(nxt,         nxt + 16384, tid, va);
            store_regs(nxt + 32768, nxt + 49152, tid, vb);
            __syncthreads();
        }
    }

    // epilogue: direct scattered float2 stores
    #pragma unroll
    for (int mt = 0; mt < 2; mt++) {
        #pragma unroll
        for (int nt = 0; nt < 8; nt++) {
            int r  = m0 + warpm * 32 + mt * 16 + (l >> 2);
            int cc = n0 + warpn * 64 + nt * 8 + 2 * (l & 3);
            float2 v0 = make_float2(acc[mt][nt][0], acc[mt][nt][1]);
            float2 v1 = make_float2(acc[mt][nt][2], acc[mt][nt][3]);
            if (PERM) {
                int b = r >> 11, s = r & 2047, h = cc >> 6, d = cc & 63;
                float* base = C + ((((size_t)(b * 32 + h)) * 2048) << 6) + d;
                *reinterpret_cast<float2*>(base + ((size_t)s << 6))       = v0;
                *reinterpret_cast<float2*>(base + ((size_t)(s + 8) << 6)) = v1;
            } else {
                *reinterpret_cast<float2*>(C + (size_t)r * 2048 + cc)       = v0;
                *reinterpret_cast<float2*>(C + (size_t)(r + 8) * 2048 + cc) = v1;
            }
        }
    }
}

// ===========================================================================
// Relative-position bucket: exact integer reimplementation of the T5 formula.
// ===========================================================================
__device__ __forceinline__ int rel_bucket(int dist /* = k - q */) {
    int rel = dist > 0 ? 16 : 0;
    int d = abs(dist);
    int sb;
    if (d < 8)       sb = d;
    else if (d < 12) sb = 8;
    else if (d < 16) sb = 9;
    else if (d < 23) sb = 10;
    else if (d < 32) sb = 11;
    else if (d < 46) sb = 12;
    else if (d < 64) sb = 13;
    else if (d < 91) sb = 14;
    else             sb = 15;
    return rel + sb;
}

__global__ void bias_table_kernel(const float* __restrict__ rel_bias) {
    int idx = blockIdx.x * blockDim.x + threadIdx.x; // over HH*4095
    if (idx >= HH * 4095) return;
    int h = idx / 4095;
    int di = idx % 4095;         // di = dist + 2047
    int bucket = rel_bucket(di - 2047);
    g_biastab[h * 4096 + di] = rel_bias[bucket * HH + h];
}

__global__ void bias_write_kernel(float* __restrict__ out_bias) {
    long long idx = (long long)blockIdx.x * blockDim.x + threadIdx.x; // float4 idx
    const int per_row4 = SS / 4;                 // 512
    long long row = idx / per_row4;              // h*SS + q
    int k = (int)(idx % per_row4) * 4;
    int h = (int)(row >> 11);
    int q = (int)(row & (SS - 1));
    const float* tab = &g_biastab[h * 4096 + 2047 - q];
    float4 v;
    v.x = tab[k + 0]; v.y = tab[k + 1]; v.z = tab[k + 2]; v.w = tab[k + 3];
    reinterpret_cast<float4*>(out_bias)[idx] = v;
}

// ===========================================================================
// Fused flash attention (fp32 SIMT, known good)
// ===========================================================================
__global__ void __launch_bounds__(256) attn_kernel()
{
    extern __shared__ float sm[];
    float (*Qs)[64] = reinterpret_cast<float(*)[64]>(sm);            // [d][qrow]
    float (*Ks)[64] = reinterpret_cast<float(*)[64]>(sm + 4096);     // [d][krow]
    float (*Vs)[64] = reinterpret_cast<float(*)[64]>(sm + 8192);     // [krow][d]
    float (*Ps)[64] = reinterpret_cast<float(*)[64]>(sm + 12288);    // [qrow][krow]
    float* bsm = sm + 16384;                                          // [128]

    const int t  = threadIdx.x;
    const int tx = t & 15, ty = t >> 4;
    const int bh = blockIdx.y;
    const int h  = bh & (HH - 1);
    const int b  = bh >> 5;
    const int q0 = blockIdx.x * 64;
    const float* qg = g_q + (size_t)bh * SS * HD;
    const float* kg = g_k + (size_t)bh * SS * HD;
    const float* vg = g_v + (size_t)bh * SS * HD;
    const float* tabh = g_biastab + h * 4096;

    #pragma unroll
    for (int rep = 0; rep < 4; rep++) {
        int lin = t + rep * 256;
        int row = lin >> 4;
        int cv  = (lin & 15) * 4;
        float4 a = *reinterpret_cast<const float4*>(&qg[(size_t)(q0 + row) * HD + cv]);
        Qs[cv + 0][row] = a.x; Qs[cv + 1][row] = a.y;
        Qs[cv + 2][row] = a.z; Qs[cv + 3][row] = a.w;
    }

    float m_i[4], l_i[4], o[4][4];
    #pragma unroll
    for (int i = 0; i < 4; i++) {
        m_i[i] = -1e30f; l_i[i] = 0.f;
        #pragma unroll
        for (int j = 0; j < 4; j++) o[i][j] = 0.f;
    }

    for (int k0 = 0; k0 < SS; k0 += 64) {
        #pragma unroll
        for (int rep = 0; rep < 4; rep++) {
            int lin = t + rep * 256;
            int row = lin >> 4;
            int cv  = (lin & 15) * 4;
            float4 a = *reinterpret_cast<const float4*>(&kg[(size_t)(k0 + row) * HD + cv]);
            Ks[cv + 0][row] = a.x; Ks[cv + 1][row] = a.y;
            Ks[cv + 2][row] = a.z; Ks[cv + 3][row] = a.w;
            float4 vv = *reinterpret_cast<const float4*>(&vg[(size_t)(k0 + row) * HD + cv]);
            *reinterpret_cast<float4*>(&Vs[row][cv]) = vv;
        }
        if (t < 128) bsm[t] = tabh[k0 - q0 + 1984 + t];
        __syncthreads();

        float sc[4][4] = {};
        #pragma unroll 8
        for (int kk = 0; kk < 64; kk++) {
            float4 qv = *reinterpret_cast<const float4*>(&Qs[kk][ty * 4]);
            float4 kv = *reinterpret_cast<const float4*>(&Ks[kk][tx * 4]);
            sc[0][0] += qv.x * kv.x; sc[0][1] += qv.x * kv.y;
            sc[0][2] += qv.x * kv.z; sc[0][3] += qv.x * kv.w;
            sc[1][0] += qv.y * kv.x; sc[1][1] += qv.y * kv.y;
            sc[1][2] += qv.y * kv.z; sc[1][3] += qv.y * kv.w;
            sc[2][0] += qv.z * kv.x; sc[2][1] += qv.z * kv.y;
            sc[2][2] += qv.z * kv.z; sc[2][3] += qv.z * kv.w;
            sc[3][0] += qv.w * kv.x; sc[3][1] += qv.w * kv.y;
            sc[3][2] += qv.w * kv.z; sc[3][3] += qv.w * kv.w;
        }

        #pragma unroll
        for (int i = 0; i < 4; i++) {
            float mx = -1e30f;
            #pragma unroll
            for (int j = 0; j < 4; j++) {
                sc[i][j] += bsm[63 + tx * 4 + j - ty * 4 - i];
                mx = fmaxf(mx, sc[i][j]);
            }
            mx = fmaxf(mx, __shfl_xor_sync(0xffffffffu, mx, 1));
            mx = fmaxf(mx, __shfl_xor_sync(0xffffffffu, mx, 2));
            mx = fmaxf(mx, __shfl_xor_sync(0xffffffffu, mx, 4));
            mx = fmaxf(mx, __shfl_xor_sync(0xffffffffu, mx, 8));
            float mnew  = fmaxf(m_i[i], mx);
            float scale = expf(m_i[i] - mnew);
            float sum = 0.f;
            #pragma unroll
            for (int j = 0; j < 4; j++) {
                float p = expf(sc[i][j] - mnew);
                sc[i][j] = p; sum += p;
            }
            sum += __shfl_xor_sync(0xffffffffu, sum, 1);
            sum += __shfl_xor_sync(0xffffffffu, sum, 2);
            sum += __shfl_xor_sync(0xffffffffu, sum, 4);
            sum += __shfl_xor_sync(0xffffffffu, sum, 8);
            l_i[i] = l_i[i] * scale + sum;
            m_i[i] = mnew;
            #pragma unroll
            for (int j = 0; j < 4; j++) o[i][j] *= scale;
            *reinterpret_cast<float4*>(&Ps[ty * 4 + i][tx * 4]) =
                make_float4(sc[i][0], sc[i][1], sc[i][2], sc[i][3]);
        }
        __syncthreads();

        #pragma unroll 8
        for (int kk = 0; kk < 64; kk++) {
            float4 vv = *reinterpret_cast<const float4*>(&Vs[kk][tx * 4]);
            #pragma unroll
            for (int i = 0; i < 4; i++) {
                float p = Ps[ty * 4 + i][kk];
                o[i][0] += p * vv.x; o[i][1] += p * vv.y;
                o[i][2] += p * vv.z; o[i][3] += p * vv.w;
            }
        }
        __syncthreads();
    }

    #pragma unroll
    for (int i = 0; i < 4; i++) {
        float inv = 1.0f / l_i[i];
        int row = q0 + ty * 4 + i;
        size_t off = ((size_t)(b * SS + row)) * MD + h * HD + tx * 4;
        *reinterpret_cast<float4*>(g_ctx + off) =
            make_float4(o[i][0] * inv, o[i][1] * inv, o[i][2] * inv, o[i][3] * inv);
    }
}

// ===========================================================================

extern "C" void kernel_launch(void* const* d_in, const int* in_sizes, int n_in,
                              void* d_out, int out_size)
{
    (void)in_sizes; (void)n_in; (void)out_size;
    const float* x  = (const float*)d_in[0];
    const float* wq = (const float*)d_in[1];
    const float* wk = (const float*)d_in[2];
    const float* wv = (const float*)d_in[3];
    const float* wo = (const float*)d_in[4];
    const float* rb = (const float*)d_in[5];
    float* out      = (float*)d_out;
    float* out_bias = out + (size_t)BB * SS * MD;

    float *qp, *kp, *vp, *cp;
    cudaGetSymbolAddress((void**)&qp, g_q);
    cudaGetSymbolAddress((void**)&kp, g_k);
    cudaGetSymbolAddress((void**)&vp, g_v);
    cudaGetSymbolAddress((void**)&cp, g_ctx);

    cudaFuncSetAttribute(attn_kernel, cudaFuncAttributeMaxDynamicSharedMemorySize, 66048);
    cudaFuncSetAttribute(gemm_mma<true>,  cudaFuncAttributeMaxDynamicSharedMemorySize, GSMEM_BYTES);
    cudaFuncSetAttribute(gemm_mma<false>, cudaFuncAttributeMaxDynamicSharedMemorySize, GSMEM_BYTES);

    bias_table_kernel<<<(HH * 4095 + 255) / 256, 256>>>(rb);

    gemm_mma<true><<<512, 256, GSMEM_BYTES>>>(x, wq, qp);
    gemm_mma<true><<<512, 256, GSMEM_BYTES>>>(x, wk, kp);
    gemm_mma<true><<<512, 256, GSMEM_BYTES>>>(x, wv, vp);

    attn_kernel<<<dim3(SS / 64, BB * HH), 256, 66048>>>();

    gemm_mma<false><<<512, 256, GSMEM_BYTES>>>(cp, wo, out);

    long long nb4 = (long long)HH * SS * (SS / 4);
    bias_write_kernel<<<(unsigned)(nb4 / 256), 256>>>(out_bias);
}

// round 4
// speedup vs baseline: 2.9697x; 1.9909x over previous
#include <cuda_runtime.h>
#include <cuda_bf16.h>
#include <cstdint>
#include <math.h>

#define BB 2
#define SS 2048
#define HH 32
#define HD 64
#define MD 2048
#define MTOT (BB*SS)

// ---------------- device scratch (static, no allocation) ----------------
__device__ __nv_bfloat16 gx_h[MTOT*MD],  gx_l[MTOT*MD];
__device__ __nv_bfloat16 gwq_h[MD*MD],   gwq_l[MD*MD];
__device__ __nv_bfloat16 gwk_h[MD*MD],   gwk_l[MD*MD];
__device__ __nv_bfloat16 gwv_h[MD*MD],   gwv_l[MD*MD];
__device__ __nv_bfloat16 gwo_h[MD*MD],   gwo_l[MD*MD];
__device__ __nv_bfloat16 gq_h[MTOT*MD],  gq_l[MTOT*MD];   // [bh][s][64]
__device__ __nv_bfloat16 gk_h[MTOT*MD],  gk_l[MTOT*MD];
__device__ __nv_bfloat16 gv_h[MTOT*MD],  gv_l[MTOT*MD];
__device__ __nv_bfloat16 gc_h[MTOT*MD],  gc_l[MTOT*MD];   // ctx [b*S+s][2048]
__device__ float g_biastab[HH*4096];

// ---------------- small helpers ----------------
__device__ __forceinline__ uint32_t smem_to_u32(const void* p) {
    uint32_t a;
    asm("{ .reg .u64 t; cvta.to.shared.u64 t, %1; cvt.u32.u64 %0, t; }" : "=r"(a) : "l"(p));
    return a;
}
__device__ __forceinline__ void cp16(uint32_t dst, const void* src) {
    asm volatile("cp.async.cg.shared.global [%0], [%1], 16;" :: "r"(dst), "l"(src));
}
__device__ __forceinline__ void cp4(uint32_t dst, const void* src) {
    asm volatile("cp.async.ca.shared.global [%0], [%1], 4;" :: "r"(dst), "l"(src));
}
#define CP_COMMIT() asm volatile("cp.async.commit_group;" ::: "memory")
#define CP_WAIT(n)  asm volatile("cp.async.wait_group %0;" :: "n"(n) : "memory")

__device__ __forceinline__ void ldx4(uint32_t* r, uint32_t addr) {
    asm volatile("ldmatrix.sync.aligned.m8n8.x4.shared.b16 {%0,%1,%2,%3}, [%4];"
                 : "=r"(r[0]), "=r"(r[1]), "=r"(r[2]), "=r"(r[3]) : "r"(addr));
}
__device__ __forceinline__ void ldx4t(uint32_t* r, uint32_t addr) {
    asm volatile("ldmatrix.sync.aligned.m8n8.x4.trans.shared.b16 {%0,%1,%2,%3}, [%4];"
                 : "=r"(r[0]), "=r"(r[1]), "=r"(r[2]), "=r"(r[3]) : "r"(addr));
}
__device__ __forceinline__ void mma_bf16(float* d, const uint32_t* a,
                                         uint32_t b0, uint32_t b1) {
    asm volatile(
        "mma.sync.aligned.m16n8k16.row.col.f32.bf16.bf16.f32 "
        "{%0,%1,%2,%3}, {%4,%5,%6,%7}, {%8,%9}, {%0,%1,%2,%3};"
        : "+f"(d[0]), "+f"(d[1]), "+f"(d[2]), "+f"(d[3])
        : "r"(a[0]), "r"(a[1]), "r"(a[2]), "r"(a[3]), "r"(b0), "r"(b1));
}

__device__ __forceinline__ uint32_t pack_hi(float a, float b) {
    return __byte_perm(__float_as_uint(a), __float_as_uint(b), 0x7632);
}
__device__ __forceinline__ uint32_t pack_lo_res(float a, float b) {
    float ra = a - __uint_as_float(__float_as_uint(a) & 0xffff0000u);
    float rb = b - __uint_as_float(__float_as_uint(b) & 0xffff0000u);
    uint32_t r;
    asm("cvt.rn.bf16x2.f32 %0, %1, %2;" : "=r"(r) : "f"(rb), "f"(ra));
    return r;
}

// fp32 -> bf16 hi/lo split (one-shot elementwise)
__global__ void convert_kernel(const float* __restrict__ in,
                               __nv_bfloat16* __restrict__ hi,
                               __nv_bfloat16* __restrict__ lo, int n4) {
    int i = blockIdx.x * blockDim.x + threadIdx.x;
    if (i >= n4) return;
    float4 f = reinterpret_cast<const float4*>(in)[i];
    reinterpret_cast<uint2*>(hi)[i] = make_uint2(pack_hi(f.x, f.y), pack_hi(f.z, f.w));
    reinterpret_cast<uint2*>(lo)[i] = make_uint2(pack_lo_res(f.x, f.y), pack_lo_res(f.z, f.w));
}

// issue one 128x64 bf16 chunk x 4 buffers via cp.async (16B, SW128 swizzled dst)
// sources pre-offset to (row r2, + hf*32 elems)
__device__ __forceinline__ void issue4(uint32_t sb,
    const __nv_bfloat16* s0, const __nv_bfloat16* s1,
    const __nv_bfloat16* s2, const __nv_bfloat16* s3, int tid)
{
    const int r2 = tid >> 1, hf = tid & 1;
    const uint32_t dd = (uint32_t)(r2 * 128 + hf * 64);
    #pragma unroll
    for (int i = 0; i < 4; i++) {
        uint32_t o = dd + i * 16; o ^= (o >> 3) & 0x70;
        cp16(sb + o,         s0 + i * 8);
        cp16(sb + 16384 + o, s1 + i * 8);
        cp16(sb + 32768 + o, s2 + i * 8);
        cp16(sb + 49152 + o, s3 + i * 8);
    }
}

// ===========================================================================
// bf16x3 GEMM: C[4096,2048] = A @ B^T. A_hi/lo [4096][2048], B_hi/lo [2048][2048].
// 128x128 tile, chunk 64, 3-stage cp.async pipeline (192KB smem).
// PERM=true: write bf16 hi/lo into [b,h,s,d] arrays. else fp32 plain C.
// ===========================================================================
#define GSMEM_BYTES (3 * 65536)

template<bool PERM>
__global__ void __launch_bounds__(256, 1) gemm3(
    const __nv_bfloat16* __restrict__ Ah, const __nv_bfloat16* __restrict__ Al,
    const __nv_bfloat16* __restrict__ Bh, const __nv_bfloat16* __restrict__ Bl,
    float* __restrict__ Cf,
    __nv_bfloat16* __restrict__ Ch, __nv_bfloat16* __restrict__ Cl)
{
    extern __shared__ char smem[];
    const uint32_t su = smem_to_u32(smem);
    const int tid = threadIdx.x;
    const int l = tid & 31, w = tid >> 5;
    const int warpm = w >> 1, warpn = w & 1;
    const int grp = l >> 3, lr = l & 7;
    const int m0 = (blockIdx.x >> 4) * 128, n0 = (blockIdx.x & 15) * 128;
    const int r2 = tid >> 1, hf = tid & 1;

    const __nv_bfloat16* pa_h = Ah + (size_t)(m0 + r2) * 2048 + hf * 32;
    const __nv_bfloat16* pa_l = Al + (size_t)(m0 + r2) * 2048 + hf * 32;
    const __nv_bfloat16* pb_h = Bh + (size_t)(n0 + r2) * 2048 + hf * 32;
    const __nv_bfloat16* pb_l = Bl + (size_t)(n0 + r2) * 2048 + hf * 32;

    issue4(su,         pa_h,      pa_l,      pb_h,      pb_l,      tid); CP_COMMIT();
    issue4(su + 65536, pa_h + 64, pa_l + 64, pb_h + 64, pb_l + 64, tid); CP_COMMIT();

    float acc[2][8][4];
    #pragma unroll
    for (int mt = 0; mt < 2; mt++)
        #pragma unroll
        for (int nt = 0; nt < 8; nt++)
            #pragma unroll
            for (int i = 0; i < 4; i++) acc[mt][nt][i] = 0.f;

    uint32_t a_row[2], b_row[4];
    #pragma unroll
    for (int mt = 0; mt < 2; mt++)
        a_row[mt] = (uint32_t)((warpm * 32 + mt * 16 + lr + (grp & 1) * 8) * 128);
    #pragma unroll
    for (int j = 0; j < 4; j++)
        b_row[j] = (uint32_t)((warpn * 64 + j * 16 + lr + (grp >> 1) * 8) * 128);
    const uint32_t a_c16 = (uint32_t)(grp >> 1) * 16;
    const uint32_t b_c16 = (uint32_t)(grp & 1) * 16;

    for (int c = 0; c < 32; c++) {
        CP_WAIT(1);
        __syncthreads();
        if (c + 2 < 32) {
            int k0 = (c + 2) * 64;
            issue4(su + (uint32_t)((c + 2) % 3) * 65536,
                   pa_h + k0, pa_l + k0, pb_h + k0, pb_l + k0, tid);
        }
        CP_COMMIT();

        const uint32_t cur = su + (uint32_t)(c % 3) * 65536;
        const uint32_t uAh = cur, uAl = cur + 16384,
                       uBh = cur + 32768, uBl = cur + 49152;

        #pragma unroll
        for (int ks = 0; ks < 4; ks++) {
            uint32_t ah[2][4], al[2][4];
            #pragma unroll
            for (int mt = 0; mt < 2; mt++) {
                uint32_t off = a_row[mt] + (uint32_t)(ks * 32) + a_c16;
                off ^= (off >> 3) & 0x70;
                ldx4(ah[mt], uAh + off);
                ldx4(al[mt], uAl + off);
            }
            uint32_t bh[4][4], bl[4][4];
            #pragma unroll
            for (int j = 0; j < 4; j++) {
                uint32_t off = b_row[j] + (uint32_t)(ks * 32) + b_c16;
                off ^= (off >> 3) & 0x70;
                ldx4(bh[j], uBh + off);
                ldx4(bl[j], uBl + off);
            }
            #pragma unroll
            for (int mt = 0; mt < 2; mt++) {
                #pragma unroll
                for (int j = 0; j < 4; j++) {
                    mma_bf16(acc[mt][2*j],   ah[mt], bh[j][0], bh[j][1]);
                    mma_bf16(acc[mt][2*j],   ah[mt], bl[j][0], bl[j][1]);
                    mma_bf16(acc[mt][2*j],   al[mt], bh[j][0], bh[j][1]);
                    mma_bf16(acc[mt][2*j+1], ah[mt], bh[j][2], bh[j][3]);
                    mma_bf16(acc[mt][2*j+1], ah[mt], bl[j][2], bl[j][3]);
                    mma_bf16(acc[mt][2*j+1], al[mt], bh[j][2], bh[j][3]);
                }
            }
        }
    }

    // epilogue
    #pragma unroll
    for (int mt = 0; mt < 2; mt++) {
        #pragma unroll
        for (int nt = 0; nt < 8; nt++) {
            int r  = m0 + warpm * 32 + mt * 16 + (l >> 2);
            int cc = n0 + warpn * 64 + nt * 8 + 2 * (l & 3);
            if (PERM) {
                int b = r >> 11, s = r & 2047, h = cc >> 6, d = cc & 63;
                size_t base = (((size_t)(b * 32 + h)) * 2048 + s) * 64 + d;
                *reinterpret_cast<uint32_t*>(Ch + base) =
                    pack_hi(acc[mt][nt][0], acc[mt][nt][1]);
                *reinterpret_cast<uint32_t*>(Cl + base) =
                    pack_lo_res(acc[mt][nt][0], acc[mt][nt][1]);
                *reinterpret_cast<uint32_t*>(Ch + base + 8 * 64) =
                    pack_hi(acc[mt][nt][2], acc[mt][nt][3]);
                *reinterpret_cast<uint32_t*>(Cl + base + 8 * 64) =
                    pack_lo_res(acc[mt][nt][2], acc[mt][nt][3]);
            } else {
                *reinterpret_cast<float2*>(Cf + (size_t)r * 2048 + cc) =
                    make_float2(acc[mt][nt][0], acc[mt][nt][1]);
                *reinterpret_cast<float2*>(Cf + (size_t)(r + 8) * 2048 + cc) =
                    make_float2(acc[mt][nt][2], acc[mt][nt][3]);
            }
        }
    }
}

// ===========================================================================
// relative-position bucket (exact integer T5 formula) + bias table / write
// ===========================================================================
__device__ __forceinline__ int rel_bucket(int dist) {
    int rel = dist > 0 ? 16 : 0;
    int d = abs(dist);
    int sb;
    if (d < 8)       sb = d;
    else if (d < 12) sb = 8;
    else if (d < 16) sb = 9;
    else if (d < 23) sb = 10;
    else if (d < 32) sb = 11;
    else if (d < 46) sb = 12;
    else if (d < 64) sb = 13;
    else if (d < 91) sb = 14;
    else             sb = 15;
    return rel + sb;
}

__global__ void bias_table_kernel(const float* __restrict__ rel_bias) {
    int idx = blockIdx.x * blockDim.x + threadIdx.x;
    if (idx >= HH * 4095) return;
    int h = idx / 4095;
    int di = idx % 4095;
    g_biastab[h * 4096 + di] = rel_bias[rel_bucket(di - 2047) * HH + h];
}

__global__ void bias_write_kernel(float* __restrict__ out_bias) {
    long long idx = (long long)blockIdx.x * blockDim.x + threadIdx.x;
    const int per_row4 = SS / 4;
    long long row = idx / per_row4;
    int k = (int)(idx % per_row4) * 4;
    int h = (int)(row >> 11);
    int q = (int)(row & (SS - 1));
    const float* tab = &g_biastab[h * 4096 + 2047 - q];
    float4 v;
    v.x = tab[k]; v.y = tab[k + 1]; v.z = tab[k + 2]; v.w = tab[k + 3];
    reinterpret_cast<float4*>(out_bias)[idx] = v;
}

// ===========================================================================
// FA2-style attention on mma.sync bf16x3. Block = one (b,h) x 128 q rows.
// 8 warps: warp w -> q rows [16w,16w+16). KV double-buffered via cp.async.
// smem: Qh 16K | Ql 16K | 2 x { Kh Kl Vh Vl } 64K | 2 x bias 1K  = 162KB
// ===========================================================================
#define ASMEM_BYTES (32768 + 2*65536 + 2*1024)

__global__ void __launch_bounds__(256, 1) attn_mma(
    __nv_bfloat16* __restrict__ Ch, __nv_bfloat16* __restrict__ Cl)
{
    extern __shared__ char smem[];
    const uint32_t su = smem_to_u32(smem);
    const int tid = threadIdx.x, l = tid & 31, w = tid >> 5;
    const int grp = l >> 3, lr = l & 7;
    const int bh = blockIdx.y, h = bh & 31, b = bh >> 5;
    const int q0 = blockIdx.x * 128;
    const size_t bhoff = (size_t)bh * SS * HD;
    const int r2 = tid >> 1, hf = tid & 1;

    // Q tiles -> smem (part of group 0)
    {
        const __nv_bfloat16* sh = gq_h + bhoff + (size_t)(q0 + r2) * 64 + hf * 32;
        const __nv_bfloat16* sl = gq_l + bhoff + (size_t)(q0 + r2) * 64 + hf * 32;
        uint32_t dd = (uint32_t)(r2 * 128 + hf * 64);
        #pragma unroll
        for (int i = 0; i < 4; i++) {
            uint32_t o = dd + i * 16; o ^= (o >> 3) & 0x70;
            cp16(su + o,         sh + i * 8);
            cp16(su + 16384 + o, sl + i * 8);
        }
    }

    // KV + bias issue for ktile kt
    auto issue_kv = [&](int kt) {
        uint32_t sb = su + 32768 + (uint32_t)(kt & 1) * 65536;
        size_t off = bhoff + (size_t)(kt * 128 + r2) * 64 + hf * 32;
        issue4(sb, gk_h + off, gk_l + off, gv_h + off, gv_l + off, tid);
        int w0 = kt * 128 - q0 + 1920;
        cp4(su + 163840 + (uint32_t)(kt & 1) * 1024 + tid * 4,
            &g_biastab[h * 4096 + w0 + tid]);
    };
    issue_kv(0); CP_COMMIT();
    issue_kv(1); CP_COMMIT();

    float o[8][4];
    #pragma unroll
    for (int nt = 0; nt < 8; nt++)
        #pragma unroll
        for (int i = 0; i < 4; i++) o[nt][i] = 0.f;
    float mrow[2] = {-1e30f, -1e30f};
    float lrow[2] = {0.f, 0.f};

    const uint32_t qbase  = (uint32_t)((w * 16 + lr + (grp & 1) * 8) * 128 + (grp >> 1) * 16);
    const uint32_t kvbase = (uint32_t)((lr + (grp >> 1) * 8) * 128 + (grp & 1) * 16);

    for (int kt = 0; kt < 16; kt++) {
        CP_WAIT(1);
        __syncthreads();
        const uint32_t SB = su + 32768 + (uint32_t)(kt & 1) * 65536;
        const float* bsm = reinterpret_cast<const float*>(smem + 163840 + (kt & 1) * 1024);

        // ---- S = Q K^T (bf16x3) ----
        float s[16][4];
        #pragma unroll
        for (int j = 0; j < 16; j++)
            #pragma unroll
            for (int i = 0; i < 4; i++) s[j][i] = 0.f;

        #pragma unroll
        for (int ks = 0; ks < 4; ks++) {
            uint32_t qo = qbase + (uint32_t)(ks * 32); qo ^= (qo >> 3) & 0x70;
            uint32_t ah[4], al[4];
            ldx4(ah, su + qo);
            ldx4(al, su + 16384 + qo);
            #pragma unroll
            for (int jj = 0; jj < 8; jj++) {
                uint32_t ko = kvbase + (uint32_t)(jj * 2048 + ks * 32);
                ko ^= (ko >> 3) & 0x70;
                uint32_t kh[4], kl[4];
                ldx4(kh, SB + ko);
                ldx4(kl, SB + 16384 + ko);
                mma_bf16(s[2*jj],   ah, kh[0], kh[1]);
                mma_bf16(s[2*jj],   ah, kl[0], kl[1]);
                mma_bf16(s[2*jj],   al, kh[0], kh[1]);
                mma_bf16(s[2*jj+1], ah, kh[2], kh[3]);
                mma_bf16(s[2*jj+1], ah, kl[2], kl[3]);
                mma_bf16(s[2*jj+1], al, kh[2], kh[3]);
            }
        }

        // ---- bias + online softmax ----
        const int bb = 127 - (w * 16 + (l >> 2)) + 2 * (l & 3);
        #pragma unroll
        for (int j = 0; j < 16; j++) {
            s[j][0] += bsm[bb + 8*j];
            s[j][1] += bsm[bb + 8*j + 1];
            s[j][2] += bsm[bb + 8*j - 8];
            s[j][3] += bsm[bb + 8*j - 7];
        }
        #pragma unroll
        for (int u = 0; u < 2; u++) {
            float mx = -1e30f;
            #pragma unroll
            for (int j = 0; j < 16; j++)
                mx = fmaxf(mx, fmaxf(s[j][2*u], s[j][2*u+1]));
            mx = fmaxf(mx, __shfl_xor_sync(0xffffffffu, mx, 1));
            mx = fmaxf(mx, __shfl_xor_sync(0xffffffffu, mx, 2));
            float mnew = fmaxf(mrow[u], mx);
            float scale = __expf(mrow[u] - mnew);
            mrow[u] = mnew;
            float sum = 0.f;
            #pragma unroll
            for (int j = 0; j < 16; j++) {
                float p0 = __expf(s[j][2*u]   - mnew);
                float p1 = __expf(s[j][2*u+1] - mnew);
                s[j][2*u] = p0; s[j][2*u+1] = p1;
                sum += p0 + p1;
            }
            sum += __shfl_xor_sync(0xffffffffu, sum, 1);
            sum += __shfl_xor_sync(0xffffffffu, sum, 2);
            lrow[u] = lrow[u] * scale + sum;
            #pragma unroll
            for (int nt = 0; nt < 8; nt++) {
                o[nt][2*u]   *= scale;
                o[nt][2*u+1] *= scale;
            }
        }

        // ---- O += P V (bf16x3); P acc fragments reused as A fragments ----
        #pragma unroll
        for (int ks = 0; ks < 8; ks++) {
            uint32_t aph[4], apl[4];
            aph[0] = pack_hi(s[2*ks][0],   s[2*ks][1]);
            aph[1] = pack_hi(s[2*ks][2],   s[2*ks][3]);
            aph[2] = pack_hi(s[2*ks+1][0], s[2*ks+1][1]);
            aph[3] = pack_hi(s[2*ks+1][2], s[2*ks+1][3]);
            apl[0] = pack_lo_res(s[2*ks][0],   s[2*ks][1]);
            apl[1] = pack_lo_res(s[2*ks][2],   s[2*ks][3]);
            apl[2] = pack_lo_res(s[2*ks+1][0], s[2*ks+1][1]);
            apl[3] = pack_lo_res(s[2*ks+1][2], s[2*ks+1][3]);
            #pragma unroll
            for (int dj = 0; dj < 4; dj++) {
                uint32_t vo = kvbase + (uint32_t)(ks * 2048 + dj * 32);
                vo ^= (vo >> 3) & 0x70;
                uint32_t vh[4], vl[4];
                ldx4t(vh, SB + 32768 + vo);
                ldx4t(vl, SB + 49152 + vo);
                mma_bf16(o[2*dj],   aph, vh[0], vh[2]);
                mma_bf16(o[2*dj],   aph, vl[0], vl[2]);
                mma_bf16(o[2*dj],   apl, vh[0], vh[2]);
                mma_bf16(o[2*dj+1], aph, vh[1], vh[3]);
                mma_bf16(o[2*dj+1], aph, vl[1], vl[3]);
                mma_bf16(o[2*dj+1], apl, vh[1], vh[3]);
            }
        }

        __syncthreads();
        if (kt + 2 < 16) issue_kv(kt + 2);
        CP_COMMIT();
    }

    // ---- epilogue: normalize, hi/lo split, store ctx ----
    const float inv0 = 1.f / lrow[0], inv1 = 1.f / lrow[1];
    const int rg0 = b * 2048 + q0 + w * 16 + (l >> 2);
    const size_t base0 = (size_t)rg0 * 2048 + h * 64 + 2 * (l & 3);
    const size_t base1 = base0 + (size_t)8 * 2048;
    #pragma unroll
    for (int nt = 0; nt < 8; nt++) {
        float a0 = o[nt][0] * inv0, a1 = o[nt][1] * inv0;
        float a2 = o[nt][2] * inv1, a3 = o[nt][3] * inv1;
        *reinterpret_cast<uint32_t*>(Ch + base0 + nt * 8) = pack_hi(a0, a1);
        *reinterpret_cast<uint32_t*>(Cl + base0 + nt * 8) = pack_lo_res(a0, a1);
        *reinterpret_cast<uint32_t*>(Ch + base1 + nt * 8) = pack_hi(a2, a3);
        *reinterpret_cast<uint32_t*>(Cl + base1 + nt * 8) = pack_lo_res(a2, a3);
    }
}

// ===========================================================================

extern "C" void kernel_launch(void* const* d_in, const int* in_sizes, int n_in,
                              void* d_out, int out_size)
{
    (void)in_sizes; (void)n_in; (void)out_size;
    const float* x  = (const float*)d_in[0];
    const float* wq = (const float*)d_in[1];
    const float* wk = (const float*)d_in[2];
    const float* wv = (const float*)d_in[3];
    const float* wo = (const float*)d_in[4];
    const float* rb = (const float*)d_in[5];
    float* out      = (float*)d_out;
    float* out_bias = out + (size_t)BB * SS * MD;

    // resolve device-global addresses
    __nv_bfloat16 *xh,*xl,*wqh,*wql,*wkh,*wkl,*wvh,*wvl,*woh,*wol;
    __nv_bfloat16 *qh,*ql,*kh,*kl,*vh,*vl,*ch,*cl;
    cudaGetSymbolAddress((void**)&xh,  gx_h);  cudaGetSymbolAddress((void**)&xl,  gx_l);
    cudaGetSymbolAddress((void**)&wqh, gwq_h); cudaGetSymbolAddress((void**)&wql, gwq_l);
    cudaGetSymbolAddress((void**)&wkh, gwk_h); cudaGetSymbolAddress((void**)&wkl, gwk_l);
    cudaGetSymbolAddress((void**)&wvh, gwv_h); cudaGetSymbolAddress((void**)&wvl, gwv_l);
    cudaGetSymbolAddress((void**)&woh, gwo_h); cudaGetSymbolAddress((void**)&wol, gwo_l);
    cudaGetSymbolAddress((void**)&qh,  gq_h);  cudaGetSymbolAddress((void**)&ql,  gq_l);
    cudaGetSymbolAddress((void**)&kh,  gk_h);  cudaGetSymbolAddress((void**)&kl,  gk_l);
    cudaGetSymbolAddress((void**)&vh,  gv_h);  cudaGetSymbolAddress((void**)&vl,  gv_l);
    cudaGetSymbolAddress((void**)&ch,  gc_h);  cudaGetSymbolAddress((void**)&cl,  gc_l);

    cudaFuncSetAttribute(gemm3<true>,  cudaFuncAttributeMaxDynamicSharedMemorySize, GSMEM_BYTES);
    cudaFuncSetAttribute(gemm3<false>, cudaFuncAttributeMaxDynamicSharedMemorySize, GSMEM_BYTES);
    cudaFuncSetAttribute(attn_mma,     cudaFuncAttributeMaxDynamicSharedMemorySize, ASMEM_BYTES);

    // one-shot conversions + bias table
    convert_kernel<<<(MTOT*MD/4 + 255)/256, 256>>>(x,  xh,  xl,  MTOT*MD/4);
    convert_kernel<<<(MD*MD/4   + 255)/256, 256>>>(wq, wqh, wql, MD*MD/4);
    convert_kernel<<<(MD*MD/4   + 255)/256, 256>>>(wk, wkh, wkl, MD*MD/4);
    convert_kernel<<<(MD*MD/4   + 255)/256, 256>>>(wv, wvh, wvl, MD*MD/4);
    convert_kernel<<<(MD*MD/4   + 255)/256, 256>>>(wo, woh, wol, MD*MD/4);
    bias_table_kernel<<<(HH*4095 + 255)/256, 256>>>(rb);

    // projections -> q/k/v (bf16 hi/lo, [b,h,s,d])
    gemm3<true><<<512, 256, GSMEM_BYTES>>>(xh, xl, wqh, wql, nullptr, qh, ql);
    gemm3<true><<<512, 256, GSMEM_BYTES>>>(xh, xl, wkh, wkl, nullptr, kh, kl);
    gemm3<true><<<512, 256, GSMEM_BYTES>>>(xh, xl, wvh, wvl, nullptr, vh, vl);

    // attention -> ctx (bf16 hi/lo)
    attn_mma<<<dim3(16, 64), 256, ASMEM_BYTES>>>(ch, cl);

    // output projection (fp32)
    gemm3<false><<<512, 256, GSMEM_BYTES>>>(ch, cl, woh, wol, out, nullptr, nullptr);

    // position_bias materialization
    long long nb4 = (long long)HH * SS * (SS / 4);
    bias_write_kernel<<<(unsigned)(nb4 / 256), 256>>>(out_bias);
}

// round 6
// speedup vs baseline: 3.2885x; 1.1074x over previous
#include <cuda_runtime.h>
#include <cuda_bf16.h>
#include <cstdint>
#include <math.h>

#define BB 2
#define SS 2048
#define HH 32
#define HD 64
#define MD 2048
#define MTOT (BB*SS)

// ---------------- device scratch (static, no allocation) ----------------
__device__ __nv_bfloat16 gx_h[MTOT*MD],  gx_l[MTOT*MD];
__device__ __nv_bfloat16 gwq_h[MD*MD],   gwq_l[MD*MD];
__device__ __nv_bfloat16 gwk_h[MD*MD],   gwk_l[MD*MD];
__device__ __nv_bfloat16 gwv_h[MD*MD],   gwv_l[MD*MD];
__device__ __nv_bfloat16 gwo_h[MD*MD],   gwo_l[MD*MD];
__device__ __nv_bfloat16 gq_h[MTOT*MD],  gq_l[MTOT*MD];   // [bh][s][64]
__device__ __nv_bfloat16 gk_h[MTOT*MD],  gk_l[MTOT*MD];
__device__ __nv_bfloat16 gv_h[MTOT*MD],  gv_l[MTOT*MD];
__device__ __nv_bfloat16 gc_h[MTOT*MD],  gc_l[MTOT*MD];   // ctx [b*S+s][2048]
__device__ float g_biastab[HH*4096];

// ---------------- small helpers ----------------
__device__ __forceinline__ uint32_t smem_to_u32(const void* p) {
    uint32_t a;
    asm("{ .reg .u64 t; cvta.to.shared.u64 t, %1; cvt.u32.u64 %0, t; }" : "=r"(a) : "l"(p));
    return a;
}
__device__ __forceinline__ void cp16(uint32_t dst, const void* src) {
    asm volatile("cp.async.cg.shared.global [%0], [%1], 16;" :: "r"(dst), "l"(src));
}
__device__ __forceinline__ void cp4(uint32_t dst, const void* src) {
    asm volatile("cp.async.ca.shared.global [%0], [%1], 4;" :: "r"(dst), "l"(src));
}
#define CP_COMMIT() asm volatile("cp.async.commit_group;" ::: "memory")
#define CP_WAIT(n)  asm volatile("cp.async.wait_group %0;" :: "n"(n) : "memory")

__device__ __forceinline__ void ldx4(uint32_t* r, uint32_t addr) {
    asm volatile("ldmatrix.sync.aligned.m8n8.x4.shared.b16 {%0,%1,%2,%3}, [%4];"
                 : "=r"(r[0]), "=r"(r[1]), "=r"(r[2]), "=r"(r[3]) : "r"(addr));
}
__device__ __forceinline__ void ldx4t(uint32_t* r, uint32_t addr) {
    asm volatile("ldmatrix.sync.aligned.m8n8.x4.trans.shared.b16 {%0,%1,%2,%3}, [%4];"
                 : "=r"(r[0]), "=r"(r[1]), "=r"(r[2]), "=r"(r[3]) : "r"(addr));
}
__device__ __forceinline__ void mma_bf16(float* d, const uint32_t* a,
                                         uint32_t b0, uint32_t b1) {
    asm volatile(
        "mma.sync.aligned.m16n8k16.row.col.f32.bf16.bf16.f32 "
        "{%0,%1,%2,%3}, {%4,%5,%6,%7}, {%8,%9}, {%0,%1,%2,%3};"
        : "+f"(d[0]), "+f"(d[1]), "+f"(d[2]), "+f"(d[3])
        : "r"(a[0]), "r"(a[1]), "r"(a[2]), "r"(a[3]), "r"(b0), "r"(b1));
}

__device__ __forceinline__ uint32_t pack_hi(float a, float b) {
    return __byte_perm(__float_as_uint(a), __float_as_uint(b), 0x7632);
}
__device__ __forceinline__ uint32_t pack_lo_res(float a, float b) {
    float ra = a - __uint_as_float(__float_as_uint(a) & 0xffff0000u);
    float rb = b - __uint_as_float(__float_as_uint(b) & 0xffff0000u);
    uint32_t r;
    asm("cvt.rn.bf16x2.f32 %0, %1, %2;" : "=r"(r) : "f"(rb), "f"(ra));
    return r;
}

// fp32 -> bf16 hi/lo split (one-shot elementwise)
__global__ void convert_kernel(const float* __restrict__ in,
                               __nv_bfloat16* __restrict__ hi,
                               __nv_bfloat16* __restrict__ lo, int n4) {
    int i = blockIdx.x * blockDim.x + threadIdx.x;
    if (i >= n4) return;
    float4 f = reinterpret_cast<const float4*>(in)[i];
    reinterpret_cast<uint2*>(hi)[i] = make_uint2(pack_hi(f.x, f.y), pack_hi(f.z, f.w));
    reinterpret_cast<uint2*>(lo)[i] = make_uint2(pack_lo_res(f.x, f.y), pack_lo_res(f.z, f.w));
}

// issue one 128x64 bf16 chunk x 4 buffers via cp.async (16B, SW128 swizzled dst)
// 256-thread variant (attention): thread t = (row t>>1, half t&1), 4x16B per buffer
__device__ __forceinline__ void issue4(uint32_t sb,
    const __nv_bfloat16* s0, const __nv_bfloat16* s1,
    const __nv_bfloat16* s2, const __nv_bfloat16* s3, int tid)
{
    const int r2 = tid >> 1, hf = tid & 1;
    const uint32_t dd = (uint32_t)(r2 * 128 + hf * 64);
    #pragma unroll
    for (int i = 0; i < 4; i++) {
        uint32_t o = dd + i * 16; o ^= (o >> 3) & 0x70;
        cp16(sb + o,         s0 + i * 8);
        cp16(sb + 16384 + o, s1 + i * 8);
        cp16(sb + 32768 + o, s2 + i * 8);
        cp16(sb + 49152 + o, s3 + i * 8);
    }
}

// 512-thread variant (GEMM): thread t = (row t>>2, quarter t&3), 2x16B per buffer
__device__ __forceinline__ void issue4w(uint32_t sb,
    const __nv_bfloat16* s0, const __nv_bfloat16* s1,
    const __nv_bfloat16* s2, const __nv_bfloat16* s3, int tid)
{
    const int r4 = tid >> 2, qf = tid & 3;
    const uint32_t dd = (uint32_t)(r4 * 128 + qf * 32);
    #pragma unroll
    for (int i = 0; i < 2; i++) {
        uint32_t o = dd + i * 16; o ^= (o >> 3) & 0x70;
        cp16(sb + o,         s0 + i * 8);
        cp16(sb + 16384 + o, s1 + i * 8);
        cp16(sb + 32768 + o, s2 + i * 8);
        cp16(sb + 49152 + o, s3 + i * 8);
    }
}

// ===========================================================================
// bf16x3 GEMM v2: 512 threads, 16 warps (4m x 4n), warp tile 32x32.
// C[4096,2048] = A @ B^T. 128x128 CTA tile, chunk 64, 3 buffers, issue c+2,
// WAIT(1): reader buffer c%3 and writer buffer (c+2)%3 always distinct.
// PERM=true: write bf16 hi/lo into [b,h,s,d] arrays. else fp32 plain C.
// ===========================================================================
#define GSMEM_BYTES (3 * 65536)

template<bool PERM>
__global__ void __launch_bounds__(512, 1) gemm3(
    const __nv_bfloat16* __restrict__ Ah, const __nv_bfloat16* __restrict__ Al,
    const __nv_bfloat16* __restrict__ Bh, const __nv_bfloat16* __restrict__ Bl,
    float* __restrict__ Cf,
    __nv_bfloat16* __restrict__ Ch, __nv_bfloat16* __restrict__ Cl)
{
    extern __shared__ char smem[];
    const uint32_t su = smem_to_u32(smem);
    const int tid = threadIdx.x;
    const int l = tid & 31, w = tid >> 5;
    const int wm = w >> 2, wn = w & 3;         // 4x4 warp grid, 32x32 tiles
    const int grp = l >> 3, lr = l & 7;
    const int m0 = (blockIdx.x >> 4) * 128, n0 = (blockIdx.x & 15) * 128;
    const int r4 = tid >> 2, qf = tid & 3;

    const __nv_bfloat16* pa_h = Ah + (size_t)(m0 + r4) * 2048 + qf * 16;
    const __nv_bfloat16* pa_l = Al + (size_t)(m0 + r4) * 2048 + qf * 16;
    const __nv_bfloat16* pb_h = Bh + (size_t)(n0 + r4) * 2048 + qf * 16;
    const __nv_bfloat16* pb_l = Bl + (size_t)(n0 + r4) * 2048 + qf * 16;

    issue4w(su,         pa_h,      pa_l,      pb_h,      pb_l,      tid); CP_COMMIT();
    issue4w(su + 65536, pa_h + 64, pa_l + 64, pb_h + 64, pb_l + 64, tid); CP_COMMIT();

    float acc[2][4][4];
    #pragma unroll
    for (int mt = 0; mt < 2; mt++)
        #pragma unroll
        for (int nt = 0; nt < 4; nt++)
            #pragma unroll
            for (int i = 0; i < 4; i++) acc[mt][nt][i] = 0.f;

    uint32_t a_row[2], b_row[2];
    #pragma unroll
    for (int mt = 0; mt < 2; mt++)
        a_row[mt] = (uint32_t)((wm * 32 + mt * 16 + lr + (grp & 1) * 8) * 128);
    #pragma unroll
    for (int j = 0; j < 2; j++)
        b_row[j] = (uint32_t)((wn * 32 + j * 16 + lr + (grp >> 1) * 8) * 128);
    const uint32_t a_c16 = (uint32_t)(grp >> 1) * 16;
    const uint32_t b_c16 = (uint32_t)(grp & 1) * 16;

    for (int c = 0; c < 32; c++) {
        CP_WAIT(1);
        __syncthreads();
        if (c + 2 < 32) {
            int k0 = (c + 2) * 64;
            issue4w(su + (uint32_t)((c + 2) % 3) * 65536,
                    pa_h + k0, pa_l + k0, pb_h + k0, pb_l + k0, tid);
        }
        CP_COMMIT();

        const uint32_t cur = su + (uint32_t)(c % 3) * 65536;
        const uint32_t uAh = cur, uAl = cur + 16384,
                       uBh = cur + 32768, uBl = cur + 49152;

        #pragma unroll
        for (int ks = 0; ks < 4; ks++) {
            uint32_t ah[2][4], al[2][4];
            #pragma unroll
            for (int mt = 0; mt < 2; mt++) {
                uint32_t off = a_row[mt] + (uint32_t)(ks * 32) + a_c16;
                off ^= (off >> 3) & 0x70;
                ldx4(ah[mt], uAh + off);
                ldx4(al[mt], uAl + off);
            }
            uint32_t bh[2][4], bl[2][4];
            #pragma unroll
            for (int j = 0; j < 2; j++) {
                uint32_t off = b_row[j] + (uint32_t)(ks * 32) + b_c16;
                off ^= (off >> 3) & 0x70;
                ldx4(bh[j], uBh + off);
                ldx4(bl[j], uBl + off);
            }
            #pragma unroll
            for (int mt = 0; mt < 2; mt++) {
                #pragma unroll
                for (int j = 0; j < 2; j++) {
                    mma_bf16(acc[mt][2*j],   ah[mt], bh[j][0], bh[j][1]);
                    mma_bf16(acc[mt][2*j],   ah[mt], bl[j][0], bl[j][1]);
                    mma_bf16(acc[mt][2*j],   al[mt], bh[j][0], bh[j][1]);
                    mma_bf16(acc[mt][2*j+1], ah[mt], bh[j][2], bh[j][3]);
                    mma_bf16(acc[mt][2*j+1], ah[mt], bl[j][2], bl[j][3]);
                    mma_bf16(acc[mt][2*j+1], al[mt], bh[j][2], bh[j][3]);
                }
            }
        }
    }

    // epilogue
    #pragma unroll
    for (int mt = 0; mt < 2; mt++) {
        #pragma unroll
        for (int nt = 0; nt < 4; nt++) {
            int r  = m0 + wm * 32 + mt * 16 + (l >> 2);
            int cc = n0 + wn * 32 + nt * 8 + 2 * (l & 3);
            if (PERM) {
                int b = r >> 11, s = r & 2047, h = cc >> 6, d = cc & 63;
                size_t base = (((size_t)(b * 32 + h)) * 2048 + s) * 64 + d;
                *reinterpret_cast<uint32_t*>(Ch + base) =
                    pack_hi(acc[mt][nt][0], acc[mt][nt][1]);
                *reinterpret_cast<uint32_t*>(Cl + base) =
                    pack_lo_res(acc[mt][nt][0], acc[mt][nt][1]);
                *reinterpret_cast<uint32_t*>(Ch + base + 8 * 64) =
                    pack_hi(acc[mt][nt][2], acc[mt][nt][3]);
                *reinterpret_cast<uint32_t*>(Cl + base + 8 * 64) =
                    pack_lo_res(acc[mt][nt][2], acc[mt][nt][3]);
            } else {
                *reinterpret_cast<float2*>(Cf + (size_t)r * 2048 + cc) =
                    make_float2(acc[mt][nt][0], acc[mt][nt][1]);
                *reinterpret_cast<float2*>(Cf + (size_t)(r + 8) * 2048 + cc) =
                    make_float2(acc[mt][nt][2], acc[mt][nt][3]);
            }
        }
    }
}

// ===========================================================================
// relative-position bucket (exact integer T5 formula) + bias table / write
// ===========================================================================
__device__ __forceinline__ int rel_bucket(int dist) {
    int rel = dist > 0 ? 16 : 0;
    int d = abs(dist);
    int sb;
    if (d < 8)       sb = d;
    else if (d < 12) sb = 8;
    else if (d < 16) sb = 9;
    else if (d < 23) sb = 10;
    else if (d < 32) sb = 11;
    else if (d < 46) sb = 12;
    else if (d < 64) sb = 13;
    else if (d < 91) sb = 14;
    else             sb = 15;
    return rel + sb;
}

__global__ void bias_table_kernel(const float* __restrict__ rel_bias) {
    int idx = blockIdx.x * blockDim.x + threadIdx.x;
    if (idx >= HH * 4095) return;
    int h = idx / 4095;
    int di = idx % 4095;
    g_biastab[h * 4096 + di] = rel_bias[rel_bucket(di - 2047) * HH + h];
}

__global__ void bias_write_kernel(float* __restrict__ out_bias) {
    long long idx = (long long)blockIdx.x * blockDim.x + threadIdx.x;
    const int per_row4 = SS / 4;
    long long row = idx / per_row4;
    int k = (int)(idx % per_row4) * 4;
    int h = (int)(row >> 11);
    int q = (int)(row & (SS - 1));
    const float* tab = &g_biastab[h * 4096 + 2047 - q];
    float4 v;
    v.x = tab[k]; v.y = tab[k + 1]; v.z = tab[k + 2]; v.w = tab[k + 3];
    reinterpret_cast<float4*>(out_bias)[idx] = v;
}

// ===========================================================================
// FA2-style attention on mma.sync bf16x3. Block = one (b,h) x 128 q rows.
// 8 warps: warp w -> q rows [16w,16w+16). KV double-buffered via cp.async.
// smem: Qh 16K | Ql 16K | 2 x { Kh Kl Vh Vl } 64K | 2 x bias 1K  = 162KB
// ===========================================================================
#define ASMEM_BYTES (32768 + 2*65536 + 2*1024)

__global__ void __launch_bounds__(256, 1) attn_mma(
    __nv_bfloat16* __restrict__ Ch, __nv_bfloat16* __restrict__ Cl)
{
    extern __shared__ char smem[];
    const uint32_t su = smem_to_u32(smem);
    const int tid = threadIdx.x, l = tid & 31, w = tid >> 5;
    const int grp = l >> 3, lr = l & 7;
    const int bh = blockIdx.y, h = bh & 31, b = bh >> 5;
    const int q0 = blockIdx.x * 128;
    const size_t bhoff = (size_t)bh * SS * HD;
    const int r2 = tid >> 1, hf = tid & 1;

    // Q tiles -> smem (part of group 0)
    {
        const __nv_bfloat16* sh = gq_h + bhoff + (size_t)(q0 + r2) * 64 + hf * 32;
        const __nv_bfloat16* sl = gq_l + bhoff + (size_t)(q0 + r2) * 64 + hf * 32;
        uint32_t dd = (uint32_t)(r2 * 128 + hf * 64);
        #pragma unroll
        for (int i = 0; i < 4; i++) {
            uint32_t o = dd + i * 16; o ^= (o >> 3) & 0x70;
            cp16(su + o,         sh + i * 8);
            cp16(su + 16384 + o, sl + i * 8);
        }
    }

    // KV + bias issue for ktile kt
    auto issue_kv = [&](int kt) {
        uint32_t sb = su + 32768 + (uint32_t)(kt & 1) * 65536;
        size_t off = bhoff + (size_t)(kt * 128 + r2) * 64 + hf * 32;
        issue4(sb, gk_h + off, gk_l + off, gv_h + off, gv_l + off, tid);
        int w0 = kt * 128 - q0 + 1920;
        cp4(su + 163840 + (uint32_t)(kt & 1) * 1024 + tid * 4,
            &g_biastab[h * 4096 + w0 + tid]);
    };
    issue_kv(0); CP_COMMIT();
    issue_kv(1); CP_COMMIT();

    float o[8][4];
    #pragma unroll
    for (int nt = 0; nt < 8; nt++)
        #pragma unroll
        for (int i = 0; i < 4; i++) o[nt][i] = 0.f;
    float mrow[2] = {-1e30f, -1e30f};
    float lrow[2] = {0.f, 0.f};

    const uint32_t qbase  = (uint32_t)((w * 16 + lr + (grp & 1) * 8) * 128 + (grp >> 1) * 16);
    const uint32_t kvbase = (uint32_t)((lr + (grp >> 1) * 8) * 128 + (grp & 1) * 16);

    for (int kt = 0; kt < 16; kt++) {
        CP_WAIT(1);
        __syncthreads();
        const uint32_t SB = su + 32768 + (uint32_t)(kt & 1) * 65536;
        const float* bsm = reinterpret_cast<const float*>(smem + 163840 + (kt & 1) * 1024);

        // ---- S = Q K^T (bf16x3) ----
        float s[16][4];
        #pragma unroll
        for (int j = 0; j < 16; j++)
            #pragma unroll
            for (int i = 0; i < 4; i++) s[j][i] = 0.f;

        #pragma unroll
        for (int ks = 0; ks < 4; ks++) {
            uint32_t qo = qbase + (uint32_t)(ks * 32); qo ^= (qo >> 3) & 0x70;
            uint32_t ah[4], al[4];
            ldx4(ah, su + qo);
            ldx4(al, su + 16384 + qo);
            #pragma unroll
            for (int jj = 0; jj < 8; jj++) {
                uint32_t ko = kvbase + (uint32_t)(jj * 2048 + ks * 32);
                ko ^= (ko >> 3) & 0x70;
                uint32_t kh[4], kl[4];
                ldx4(kh, SB + ko);
                ldx4(kl, SB + 16384 + ko);
                mma_bf16(s[2*jj],   ah, kh[0], kh[1]);
                mma_bf16(s[2*jj],   ah, kl[0], kl[1]);
                mma_bf16(s[2*jj],   al, kh[0], kh[1]);
                mma_bf16(s[2*jj+1], ah, kh[2], kh[3]);
                mma_bf16(s[2*jj+1], ah, kl[2], kl[3]);
                mma_bf16(s[2*jj+1], al, kh[2], kh[3]);
            }
        }

        // ---- bias + online softmax ----
        const int bb = 127 - (w * 16 + (l >> 2)) + 2 * (l & 3);
        #pragma unroll
        for (int j = 0; j < 16; j++) {
            s[j][0] += bsm[bb + 8*j];
            s[j][1] += bsm[bb + 8*j + 1];
            s[j][2] += bsm[bb + 8*j - 8];
            s[j][3] += bsm[bb + 8*j - 7];
        }
        #pragma unroll
        for (int u = 0; u < 2; u++) {
            float mx = -1e30f;
            #pragma unroll
            for (int j = 0; j < 16; j++)
                mx = fmaxf(mx, fmaxf(s[j][2*u], s[j][2*u+1]));
            mx = fmaxf(mx, __shfl_xor_sync(0xffffffffu, mx, 1));
            mx = fmaxf(mx, __shfl_xor_sync(0xffffffffu, mx, 2));
            float mnew = fmaxf(mrow[u], mx);
            float scale = __expf(mrow[u] - mnew);
            mrow[u] = mnew;
            float sum = 0.f;
            #pragma unroll
            for (int j = 0; j < 16; j++) {
                float p0 = __expf(s[j][2*u]   - mnew);
                float p1 = __expf(s[j][2*u+1] - mnew);
                s[j][2*u] = p0; s[j][2*u+1] = p1;
                sum += p0 + p1;
            }
            sum += __shfl_xor_sync(0xffffffffu, sum, 1);
            sum += __shfl_xor_sync(0xffffffffu, sum, 2);
            lrow[u] = lrow[u] * scale + sum;
            #pragma unroll
            for (int nt = 0; nt < 8; nt++) {
                o[nt][2*u]   *= scale;
                o[nt][2*u+1] *= scale;
            }
        }

        // ---- O += P V (bf16x3); P acc fragments reused as A fragments ----
        #pragma unroll
        for (int ks = 0; ks < 8; ks++) {
            uint32_t aph[4], apl[4];
            aph[0] = pack_hi(s[2*ks][0],   s[2*ks][1]);
            aph[1] = pack_hi(s[2*ks][2],   s[2*ks][3]);
            aph[2] = pack_hi(s[2*ks+1][0], s[2*ks+1][1]);
            aph[3] = pack_hi(s[2*ks+1][2], s[2*ks+1][3]);
            apl[0] = pack_lo_res(s[2*ks][0],   s[2*ks][1]);
            apl[1] = pack_lo_res(s[2*ks][2],   s[2*ks][3]);
            apl[2] = pack_lo_res(s[2*ks+1][0], s[2*ks+1][1]);
            apl[3] = pack_lo_res(s[2*ks+1][2], s[2*ks+1][3]);
            #pragma unroll
            for (int dj = 0; dj < 4; dj++) {
                uint32_t vo = kvbase + (uint32_t)(ks * 2048 + dj * 32);
                vo ^= (vo >> 3) & 0x70;
                uint32_t vh[4], vl[4];
                ldx4t(vh, SB + 32768 + vo);
                ldx4t(vl, SB + 49152 + vo);
                mma_bf16(o[2*dj],   aph, vh[0], vh[2]);
                mma_bf16(o[2*dj],   aph, vl[0], vl[2]);
                mma_bf16(o[2*dj],   apl, vh[0], vh[2]);
                mma_bf16(o[2*dj+1], aph, vh[1], vh[3]);
                mma_bf16(o[2*dj+1], aph, vl[1], vl[3]);
                mma_bf16(o[2*dj+1], apl, vh[1], vh[3]);
            }
        }

        __syncthreads();
        if (kt + 2 < 16) issue_kv(kt + 2);
        CP_COMMIT();
    }

    // ---- epilogue: normalize, hi/lo split, store ctx ----
    const float inv0 = 1.f / lrow[0], inv1 = 1.f / lrow[1];
    const int rg0 = b * 2048 + q0 + w * 16 + (l >> 2);
    const size_t base0 = (size_t)rg0 * 2048 + h * 64 + 2 * (l & 3);
    const size_t base1 = base0 + (size_t)8 * 2048;
    #pragma unroll
    for (int nt = 0; nt < 8; nt++) {
        float a0 = o[nt][0] * inv0, a1 = o[nt][1] * inv0;
        float a2 = o[nt][2] * inv1, a3 = o[nt][3] * inv1;
        *reinterpret_cast<uint32_t*>(Ch + base0 + nt * 8) = pack_hi(a0, a1);
        *reinterpret_cast<uint32_t*>(Cl + base0 + nt * 8) = pack_lo_res(a0, a1);
        *reinterpret_cast<uint32_t*>(Ch + base1 + nt * 8) = pack_hi(a2, a3);
        *reinterpret_cast<uint32_t*>(Cl + base1 + nt * 8) = pack_lo_res(a2, a3);
    }
}

// ===========================================================================

extern "C" void kernel_launch(void* const* d_in, const int* in_sizes, int n_in,
                              void* d_out, int out_size)
{
    (void)in_sizes; (void)n_in; (void)out_size;
    const float* x  = (const float*)d_in[0];
    const float* wq = (const float*)d_in[1];
    const float* wk = (const float*)d_in[2];
    const float* wv = (const float*)d_in[3];
    const float* wo = (const float*)d_in[4];
    const float* rb = (const float*)d_in[5];
    float* out      = (float*)d_out;
    float* out_bias = out + (size_t)BB * SS * MD;

    // resolve device-global addresses
    __nv_bfloat16 *xh,*xl,*wqh,*wql,*wkh,*wkl,*wvh,*wvl,*woh,*wol;
    __nv_bfloat16 *qh,*ql,*kh,*kl,*vh,*vl,*ch,*cl;
    cudaGetSymbolAddress((void**)&xh,  gx_h);  cudaGetSymbolAddress((void**)&xl,  gx_l);
    cudaGetSymbolAddress((void**)&wqh, gwq_h); cudaGetSymbolAddress((void**)&wql, gwq_l);
    cudaGetSymbolAddress((void**)&wkh, gwk_h); cudaGetSymbolAddress((void**)&wkl, gwk_l);
    cudaGetSymbolAddress((void**)&wvh, gwv_h); cudaGetSymbolAddress((void**)&wvl, gwv_l);
    cudaGetSymbolAddress((void**)&woh, gwo_h); cudaGetSymbolAddress((void**)&wol, gwo_l);
    cudaGetSymbolAddress((void**)&qh,  gq_h);  cudaGetSymbolAddress((void**)&ql,  gq_l);
    cudaGetSymbolAddress((void**)&kh,  gk_h);  cudaGetSymbolAddress((void**)&kl,  gk_l);
    cudaGetSymbolAddress((void**)&vh,  gv_h);  cudaGetSymbolAddress((void**)&vl,  gv_l);
    cudaGetSymbolAddress((void**)&ch,  gc_h);  cudaGetSymbolAddress((void**)&cl,  gc_l);

    cudaFuncSetAttribute(gemm3<true>,  cudaFuncAttributeMaxDynamicSharedMemorySize, GSMEM_BYTES);
    cudaFuncSetAttribute(gemm3<false>, cudaFuncAttributeMaxDynamicSharedMemorySize, GSMEM_BYTES);
    cudaFuncSetAttribute(attn_mma,     cudaFuncAttributeMaxDynamicSharedMemorySize, ASMEM_BYTES);

    // one-shot conversions + bias table
    convert_kernel<<<(MTOT*MD/4 + 255)/256, 256>>>(x,  xh,  xl,  MTOT*MD/4);
    convert_kernel<<<(MD*MD/4   + 255)/256, 256>>>(wq, wqh, wql, MD*MD/4);
    convert_kernel<<<(MD*MD/4   + 255)/256, 256>>>(wk, wkh, wkl, MD*MD/4);
    convert_kernel<<<(MD*MD/4   + 255)/256, 256>>>(wv, wvh, wvl, MD*MD/4);
    convert_kernel<<<(MD*MD/4   + 255)/256, 256>>>(wo, woh, wol, MD*MD/4);
    bias_table_kernel<<<(HH*4095 + 255)/256, 256>>>(rb);

    // projections -> q/k/v (bf16 hi/lo, [b,h,s,d])
    gemm3<true><<<512, 512, GSMEM_BYTES>>>(xh, xl, wqh, wql, nullptr, qh, ql);
    gemm3<true><<<512, 512, GSMEM_BYTES>>>(xh, xl, wkh, wkl, nullptr, kh, kl);
    gemm3<true><<<512, 512, GSMEM_BYTES>>>(xh, xl, wvh, wvl, nullptr, vh, vl);

    // attention -> ctx (bf16 hi/lo)
    attn_mma<<<dim3(16, 64), 256, ASMEM_BYTES>>>(ch, cl);

    // output projection (fp32)
    gemm3<false><<<512, 512, GSMEM_BYTES>>>(ch, cl, woh, wol, out, nullptr, nullptr);

    // position_bias materialization
    long long nb4 = (long long)HH * SS * (SS / 4);
    bias_write_kernel<<<(unsigned)(nb4 / 256), 256>>>(out_bias);
}